// round 13
// baseline (speedup 1.0000x reference)
#include <cuda_runtime.h>
#include <cuda_bf16.h>

#define NN 9216
#define WW 96
#define NB 8192
#define CAP 32

// Scratch (no cudaMalloc allowed). g_hist re-zeroed by scan_kernel each replay.
__device__ unsigned      g_hist[NB];
__device__ unsigned      g_binstart[NB];
__device__ unsigned      g_bincnt[NB];
__device__ unsigned      g_list[NB * CAP];
__device__ unsigned char g_keep[NN];

// ---------------------------------------------------------------------------
// Bucket rank stage 1 (proven R3)
// ---------------------------------------------------------------------------
__global__ void __launch_bounds__(256) hist_kernel(const float* __restrict__ cls) {
    int c = blockIdx.x * 256 + threadIdx.x;
    float s = cls[c];
    int bin = min((int)(s * 8192.0f), NB - 1);
    unsigned slot = atomicAdd(&g_hist[bin], 1u);
    if (slot < CAP) g_list[bin * CAP + slot] = (unsigned)c;
}

// ---------------------------------------------------------------------------
// Bucket rank stage 2: shuffle-based block scan (proven R10)
// ---------------------------------------------------------------------------
__global__ void __launch_bounds__(1024) scan_kernel() {
    __shared__ unsigned wsum[32];
    const int t = threadIdx.x;
    const int lane = t & 31, wid = t >> 5;

    unsigned v[8], sum = 0;
    #pragma unroll
    for (int i = 0; i < 8; i++) { v[i] = g_hist[t * 8 + i]; sum += v[i]; }

    unsigned s = sum;
    #pragma unroll
    for (int off = 1; off < 32; off <<= 1) {
        unsigned n = __shfl_up_sync(0xFFFFFFFFu, s, off);
        if (lane >= off) s += n;
    }
    if (lane == 31) wsum[wid] = s;
    __syncthreads();
    if (wid == 0) {
        unsigned ws = wsum[lane];
        #pragma unroll
        for (int off = 1; off < 32; off <<= 1) {
            unsigned n = __shfl_up_sync(0xFFFFFFFFu, ws, off);
            if (lane >= off) ws += n;
        }
        wsum[lane] = ws;
    }
    __syncthreads();
    unsigned run = (wid ? wsum[wid - 1] : 0u) + s - sum;
    #pragma unroll
    for (int i = 0; i < 8; i++) {
        run += v[i];
        g_binstart[t * 8 + i] = NN - run;
        g_bincnt[t * 8 + i]   = v[i];
        g_hist[t * 8 + i]     = 0;
    }
}

// ---------------------------------------------------------------------------
// NMS: deterministic barrier-round engine (R9 decision logic) with:
//  - dual-copy bit rows (copy A bit x+2, copy B bit x+18): every tile's 9-bit
//    window lives in ONE word of one copy -> 1 LDS + shift per row per array
//  - row stride 9 words (odd) -> bank-conflict-free across rows/lanes
//  - regional warp ownership (24x12 per warp) -> warps retire as regions finish
//  - padded rows (+2 top/bottom) -> no bounds checks
// ---------------------------------------------------------------------------
#define RSTRIDE 9
#define PROWS   100

__device__ __forceinline__ void set_bit2(unsigned* arr, int x, int pr) {
    int pa = x + 2;
    atomicOr(&arr[pr * RSTRIDE + (pa >> 5)], 1u << (pa & 31));
    int pb = x + 18;
    atomicOr(&arr[pr * RSTRIDE + 4 + (pb >> 5)], 1u << (pb & 31));
}

__global__ void __launch_bounds__(1024, 1) nms_kernel(const float* __restrict__ cls) {
    extern __shared__ float sc[];   // 9216 floats (dynamic; needs func attribute)
    __shared__ unsigned dec1[PROWS * RSTRIDE], kept1[PROWS * RSTRIDE];
    __shared__ unsigned dec2[PROWS * RSTRIDE], kept2[PROWS * RSTRIDE];

    const int t    = threadIdx.x;
    const int lane = t & 31, wid = t >> 5;
    // Regional mapping: warp grid 4x8 regions of 24x12; lane grid 8x4 tiles.
    const int TX = (wid & 3) * 8 + (lane & 7);    // 0..31
    const int TY = (wid >> 2) * 4 + (lane >> 3);  // 0..31
    const int x0 = 3 * TX, y0 = 3 * TY;
    // Window word/shift: copy A iff (x0&31)<=23, else copy B. Shift always <=23.
    const int mm = x0 & 31;
    const int wsel = (mm <= 23) ? (x0 >> 5) : (4 + ((x0 + 16) >> 5));
    const int sh   = (mm <= 23) ? mm : ((x0 + 16) & 31);

    for (int i = t; i < PROWS * RSTRIDE; i += 1024) {
        dec1[i] = 0; kept1[i] = 0; dec2[i] = 0; kept2[i] = 0;
    }
    __syncthreads();

    // ---- Load scores; ballot-init invalid cells (32-cell runs per warp) ----
    #pragma unroll
    for (int k = 0; k < 9; k++) {
        int c = t + k * 1024;
        float s = cls[c];
        sc[c] = s;
        unsigned invb = __ballot_sync(0xFFFFFFFFu, !(s > 0.6f));
        if (lane == 0 && invb) {
            int y = c / WW, xs = c % WW;        // xs in {0,32,64}
            int base = (y + 2) * RSTRIDE;
            int wA = xs >> 5;
            atomicOr(&dec1[base + wA], invb << 2);
            atomicOr(&dec2[base + wA], invb << 2);
            if (invb >> 30) {
                atomicOr(&dec1[base + wA + 1], invb >> 30);
                atomicOr(&dec2[base + wA + 1], invb >> 30);
            }
            int wB = 4 + ((xs + 18) >> 5);
            atomicOr(&dec1[base + wB], invb << 18);
            atomicOr(&dec2[base + wB], invb << 18);
            atomicOr(&dec1[base + wB + 1], invb >> 14);
            atomicOr(&dec2[base + wB + 1], invb >> 14);
        }
    }
    __syncthreads();

    // ---- Build masks (exact integer geometry, 21x21 boxes — proven logic) ----
    unsigned m1[9];
    unsigned long long m2all = 0;
    unsigned pend = 0;
    #pragma unroll
    for (int k = 0; k < 9; k++) {
        int ry = k / 3, cx = k % 3;
        int x = x0 + cx, y = y0 + ry;
        int c = y * WW + x;
        float s = sc[c];
        unsigned mm1 = 0, n2 = 0;
        if (s > 0.6f) {
            pend |= 1u << k;
            int xm = x % 3, ym = y % 3;
            #define EARLIER(n) (sc[(n)] > s || (sc[(n)] == s && (n) < c))
            if (x > 0  && EARLIER(c - 1))  { mm1 |= 1u << 11; if (xm != 2) n2 |= 2u; }
            if (x < 95 && EARLIER(c + 1))  { mm1 |= 1u << 13; if (xm != 1) n2 |= 4u; }
            if (y > 0  && EARLIER(c - 96)) { mm1 |= 1u << 7;  if (ym != 2) n2 |= 1u; }
            if (y < 95 && EARLIER(c + 96)) { mm1 |= 1u << 17; if (ym != 1) n2 |= 8u; }
            if (x > 1  && xm == 1 && EARLIER(c - 2))   mm1 |= 1u << 10;
            if (x < 94 && xm == 2 && EARLIER(c + 2))   mm1 |= 1u << 14;
            if (y > 1  && ym == 1 && EARLIER(c - 192)) mm1 |= 1u << 2;
            if (y < 94 && ym == 2 && EARLIER(c + 192)) mm1 |= 1u << 22;
            bool sxp4 = (xm == 1), sxm4 = (xm == 2), syp4 = (ym == 1), sym4 = (ym == 2);
            if (x > 0  && y > 0  && !(sxm4 && sym4) && EARLIER(c - 97)) mm1 |= 1u << 6;
            if (x < 95 && y > 0  && !(sxp4 && sym4) && EARLIER(c - 95)) mm1 |= 1u << 8;
            if (x > 0  && y < 95 && !(sxm4 && syp4) && EARLIER(c + 95)) mm1 |= 1u << 16;
            if (x < 95 && y < 95 && !(sxp4 && syp4) && EARLIER(c + 97)) mm1 |= 1u << 18;
            #undef EARLIER
        }
        m1[k] = mm1;
        m2all |= (unsigned long long)n2 << (4 * k);
    }
    __syncthreads();

    unsigned p1 = pend, p2 = pend, keep9 = 0;

    // ---- Barrier rounds (2 sweeps per round) ----
    for (;;) {
        #pragma unroll
        for (int rep = 0; rep < 2; rep++) {
            if (p1) {
                unsigned dw[7], kw[7];
                #pragma unroll
                for (int r = 0; r < 7; r++) {
                    int base = (y0 + r) * RSTRIDE + wsel;   // padded row y0-2+r -> y0+r
                    dw[r] = (dec1[base]  >> sh) & 0x1FFu;
                    kw[r] = (kept1[base] >> sh) & 0x1FFu;
                }
                #pragma unroll
                for (int k = 0; k < 9; k++) {
                    if (!(p1 & (1u << k))) continue;
                    int ry = k / 3, cx = k % 3;
                    unsigned mk = m1[k], supp = 0, und = 0;
                    #pragma unroll
                    for (int r = 0; r < 5; r++) {
                        unsigned mrow = (mk >> (5 * r)) & 31u;
                        supp |= mrow & (kw[ry + r] >> cx);
                        und  |= mrow & ((~dw[ry + r]) >> cx);
                    }
                    int x = x0 + cx, pr = y0 + ry + 2;
                    if (supp) {
                        set_bit2(dec1, x, pr); set_bit2(dec2, x, pr);
                        dw[ry + 2] |= 1u << (cx + 2);
                        p1 &= ~(1u << k); p2 &= ~(1u << k);
                    } else if (!und) {
                        set_bit2(dec1, x, pr); set_bit2(kept1, x, pr);
                        dw[ry + 2] |= 1u << (cx + 2);
                        kw[ry + 2] |= 1u << (cx + 2);
                        p1 &= ~(1u << k);
                    }
                }
            }
            unsigned ready = p2 & ~p1;
            if (ready) {
                unsigned dw[7], kw[7];
                #pragma unroll
                for (int r = 0; r < 7; r++) {
                    int base = (y0 + r) * RSTRIDE + wsel;
                    dw[r] = (dec2[base]  >> sh) & 0x1FFu;
                    kw[r] = (kept2[base] >> sh) & 0x1FFu;
                }
                #pragma unroll
                for (int k = 0; k < 9; k++) {
                    if (!(ready & (1u << k))) continue;
                    int ry = k / 3, cx = k % 3;
                    unsigned n2 = (unsigned)(m2all >> (4 * k)) & 15u;
                    unsigned supp =
                          ((n2 >> 0) & (kw[ry + 1] >> (cx + 2)))
                        | ((n2 >> 1) & (kw[ry + 2] >> (cx + 1)))
                        | ((n2 >> 2) & (kw[ry + 2] >> (cx + 3)))
                        | ((n2 >> 3) & (kw[ry + 3] >> (cx + 2)));
                    unsigned und =
                          ((n2 >> 0) & ((~dw[ry + 1]) >> (cx + 2)))
                        | ((n2 >> 1) & ((~dw[ry + 2]) >> (cx + 1)))
                        | ((n2 >> 2) & ((~dw[ry + 2]) >> (cx + 3)))
                        | ((n2 >> 3) & ((~dw[ry + 3]) >> (cx + 2)));
                    int x = x0 + cx, pr = y0 + ry + 2;
                    if (supp & 1u) {
                        set_bit2(dec2, x, pr);
                        dw[ry + 2] |= 1u << (cx + 2);
                        p2 &= ~(1u << k);
                    } else if (!(und & 1u)) {
                        set_bit2(dec2, x, pr); set_bit2(kept2, x, pr);
                        dw[ry + 2] |= 1u << (cx + 2);
                        kw[ry + 2] |= 1u << (cx + 2);
                        keep9 |= 1u << k;
                        p2 &= ~(1u << k);
                    }
                }
            }
        }
        if (__syncthreads_and((p1 | p2) == 0)) break;
    }

    #pragma unroll
    for (int k = 0; k < 9; k++) {
        int c = (y0 + k / 3) * WW + x0 + (k % 3);
        g_keep[c] = (keep9 >> k) & 1u;
    }
}

// ---------------------------------------------------------------------------
// Epilogue (R3 config + singleton-bin fast path)
// ---------------------------------------------------------------------------
__global__ void __launch_bounds__(256) epi_kernel(const float* __restrict__ cls,
                                                  const float* __restrict__ reg,
                                                  float* __restrict__ out) {
    const int c = blockIdx.x * 256 + threadIdx.x;
    float s  = cls[c];
    int bin  = min((int)(s * 8192.0f), NB - 1);
    unsigned rank = g_binstart[bin];
    unsigned cnt  = min(g_bincnt[bin], (unsigned)CAP);
    if (cnt > 1u) {
        for (unsigned j = 0; j < cnt; j++) {
            int idx = (int)g_list[bin * CAP + j];
            float sj = cls[idx];
            rank += (sj > s) || (sj == s && idx < c);
        }
    }
    float kq = g_keep[c] ? 1.0f : 0.0f;
    int x = c % WW, y = c / WW;
    float X1 = rintf((2.0f * x) / 0.6f);
    float X2 = rintf((2.0f * x + 12.0f) / 0.6f);
    float Y1 = rintf((2.0f * y) / 0.6f);
    float Y2 = rintf((2.0f * y + 12.0f) / 0.6f);
    float bw = X2 - X1 + 1.0f;
    float bh = Y2 - Y1 + 1.0f;
    float4 d = ((const float4*)reg)[c];
    float* o = out + (int)rank * 5;
    o[0] = (X1 + d.x * bw) * kq;
    o[1] = (Y1 + d.y * bh) * kq;
    o[2] = (X2 + d.z * bw) * kq;
    o[3] = (Y2 + d.w * bh) * kq;
    o[4] = s * kq;
}

extern "C" void kernel_launch(void* const* d_in, const int* in_sizes, int n_in,
                              void* d_out, int out_size) {
    const float* cls = (const float*)d_in[0];
    const float* reg = (const float*)d_in[1];
    if (n_in >= 2 && in_sizes[0] > in_sizes[1]) {   // defensive: metadata order
        const float* t = cls; cls = reg; reg = t;
    }
    float* out = (float*)d_out;

    // Required: static (~14.4KB) + dynamic (36.9KB) shared exceeds the default
    // 48KB budget; this attribute set is host-side and graph-capture-safe (R4).
    cudaFuncSetAttribute(nms_kernel,
                         cudaFuncAttributeMaxDynamicSharedMemorySize,
                         NN * sizeof(float));

    hist_kernel<<<36, 256>>>(cls);
    scan_kernel<<<1, 1024>>>();
    nms_kernel<<<1, 1024, NN * sizeof(float)>>>(cls);
    epi_kernel<<<36, 256>>>(cls, reg, out);
}

// round 14
// speedup vs baseline: 1.3859x; 1.3859x over previous
#include <cuda_runtime.h>
#include <cuda_bf16.h>

#define NN 9216
#define WW 96
#define NB 8192
#define CAP 8

// Dynamic shared layout (200704 B total, needs func attribute):
//   [0)      float    sc[9216]      36864
//   [36864)  unsigned hist[8192]    32768   (packed binstart | cnt<<16 after scan)
//   [69632)  ushort   list[8192*8] 131072
#define SMEM_BYTES 200704

__device__ __forceinline__ void set_bit_s(unsigned* arr, int x, int y) {
    int p = x + 2;
    atomicOr(&arr[y * 4 + (p >> 5)], 1u << (p & 31));
}

__global__ void __launch_bounds__(1024, 1) fused_kernel(const float* __restrict__ cls,
                                                        const float* __restrict__ reg,
                                                        float* __restrict__ out) {
    extern __shared__ unsigned char dynsmem[];
    float*          sc   = (float*)dynsmem;
    unsigned*       hist = (unsigned*)(dynsmem + 36864);
    unsigned short* list = (unsigned short*)(dynsmem + 69632);

    // Hot fixpoint state: STATIC shared (R9-proven band-mapped engine).
    __shared__ unsigned dec1[WW * 4], kept1[WW * 4], dec2[WW * 4], kept2[WW * 4];
    __shared__ unsigned wsum[32];

    const int t    = threadIdx.x;
    const int lane = t & 31, wid = t >> 5;
    const int tx = t & 31, ty = t >> 5;          // band mapping (R9)
    const int x0 = 3 * tx, y0 = 3 * ty;
    const int w  = x0 >> 5, sh = x0 & 31;

    // ---- Phase 0: zero hist + bit arrays ----
    #pragma unroll
    for (int i = 0; i < 8; i++) hist[t * 8 + i] = 0;
    if (t < WW * 4) { dec1[t] = 0; kept1[t] = 0; dec2[t] = 0; kept2[t] = 0; }
    __syncthreads();

    // ---- Phase 1: load scores; shared histogram + tie lists ----
    // bin = (int)(s*8192) monotone in s; ties resolved exactly in epilogue.
    #pragma unroll
    for (int k = 0; k < 9; k++) {
        int c = t + k * 1024;
        float s = cls[c];
        sc[c] = s;
        int bin = min((int)(s * 8192.0f), NB - 1);
        unsigned slot = atomicAdd(&hist[bin], 1u);
        if (slot < CAP) list[bin * CAP + slot] = (unsigned short)c;
    }
    __syncthreads();

    // ---- Phase 2: 8192-bin scan (shuffle-based, R10-proven) ----
    {
        unsigned v[8], sum = 0;
        #pragma unroll
        for (int i = 0; i < 8; i++) { v[i] = hist[t * 8 + i]; sum += v[i]; }
        unsigned s = sum;
        #pragma unroll
        for (int off = 1; off < 32; off <<= 1) {
            unsigned n = __shfl_up_sync(0xFFFFFFFFu, s, off);
            if (lane >= off) s += n;
        }
        if (lane == 31) wsum[wid] = s;
        __syncthreads();
        if (wid == 0) {
            unsigned ws = wsum[lane];
            #pragma unroll
            for (int off = 1; off < 32; off <<= 1) {
                unsigned n = __shfl_up_sync(0xFFFFFFFFu, ws, off);
                if (lane >= off) ws += n;
            }
            wsum[lane] = ws;
        }
        __syncthreads();
        unsigned run = (wid ? wsum[wid - 1] : 0u) + s - sum;
        #pragma unroll
        for (int i = 0; i < 8; i++) {
            run += v[i];
            hist[t * 8 + i] = (unsigned)(NN - run) | (v[i] << 16);
        }
    }
    // (no barrier needed before build: build reads only sc; epilogue is after
    //  the fixpoint barriers)

    // ---- Phase 3: build masks + init invalid cells (proven R9 logic) ----
    unsigned m1[9];
    unsigned long long m2all = 0;   // 4 bits/cell: up,left,right,down (thr 0.7)
    unsigned pend = 0;
    #pragma unroll
    for (int k = 0; k < 9; k++) {
        int ry = k / 3, cx = k % 3;
        int x = x0 + cx, y = y0 + ry;
        int c = y * WW + x;
        float s = sc[c];
        unsigned mm1 = 0, n2 = 0;
        if (s > 0.6f) {
            pend |= 1u << k;
            int xm = x % 3, ym = y % 3;
            #define EARLIER(n) (sc[(n)] > s || (sc[(n)] == s && (n) < c))
            if (x > 0  && EARLIER(c - 1))  { mm1 |= 1u << 11; if (xm != 2) n2 |= 2u; }
            if (x < 95 && EARLIER(c + 1))  { mm1 |= 1u << 13; if (xm != 1) n2 |= 4u; }
            if (y > 0  && EARLIER(c - 96)) { mm1 |= 1u << 7;  if (ym != 2) n2 |= 1u; }
            if (y < 95 && EARLIER(c + 96)) { mm1 |= 1u << 17; if (ym != 1) n2 |= 8u; }
            if (x > 1  && xm == 1 && EARLIER(c - 2))   mm1 |= 1u << 10;
            if (x < 94 && xm == 2 && EARLIER(c + 2))   mm1 |= 1u << 14;
            if (y > 1  && ym == 1 && EARLIER(c - 192)) mm1 |= 1u << 2;
            if (y < 94 && ym == 2 && EARLIER(c + 192)) mm1 |= 1u << 22;
            bool sxp4 = (xm == 1), sxm4 = (xm == 2), syp4 = (ym == 1), sym4 = (ym == 2);
            if (x > 0  && y > 0  && !(sxm4 && sym4) && EARLIER(c - 97)) mm1 |= 1u << 6;
            if (x < 95 && y > 0  && !(sxp4 && sym4) && EARLIER(c - 95)) mm1 |= 1u << 8;
            if (x > 0  && y < 95 && !(sxm4 && syp4) && EARLIER(c + 95)) mm1 |= 1u << 16;
            if (x < 95 && y < 95 && !(sxp4 && syp4) && EARLIER(c + 97)) mm1 |= 1u << 18;
            #undef EARLIER
        } else {
            set_bit_s(dec1, x, y);
            set_bit_s(dec2, x, y);
        }
        m1[k] = mm1;
        m2all |= (unsigned long long)n2 << (4 * k);
    }
    __syncthreads();

    // ---- Phase 4: deterministic barrier rounds (byte-equal R9 engine) ----
    unsigned p1 = pend, p2 = pend;
    for (;;) {
        #pragma unroll
        for (int rep = 0; rep < 2; rep++) {
            if (p1) {
                unsigned dw[7], kw[7];
                #pragma unroll
                for (int r = 0; r < 7; r++) {
                    int ry = y0 - 2 + r;
                    if ((unsigned)ry < WW) {
                        int base = ry * 4 + w;
                        dw[r] = __funnelshift_r(dec1[base],  dec1[base + 1],  sh) & 0x1FFu;
                        kw[r] = __funnelshift_r(kept1[base], kept1[base + 1], sh) & 0x1FFu;
                    } else { dw[r] = 0; kw[r] = 0; }
                }
                #pragma unroll
                for (int k = 0; k < 9; k++) {
                    if (!(p1 & (1u << k))) continue;
                    int ry = k / 3, cx = k % 3;
                    unsigned mk = m1[k], supp = 0, und = 0;
                    #pragma unroll
                    for (int r = 0; r < 5; r++) {
                        unsigned mrow = (mk >> (5 * r)) & 31u;
                        supp |= mrow & (kw[ry + r] >> cx);
                        und  |= mrow & ((~dw[ry + r]) >> cx);
                    }
                    int x = x0 + cx, y = y0 + ry;
                    if (supp) {
                        set_bit_s(dec1, x, y); set_bit_s(dec2, x, y);
                        dw[ry + 2] |= 1u << (cx + 2);
                        p1 &= ~(1u << k); p2 &= ~(1u << k);
                    } else if (!und) {
                        set_bit_s(dec1, x, y); set_bit_s(kept1, x, y);
                        dw[ry + 2] |= 1u << (cx + 2);
                        kw[ry + 2] |= 1u << (cx + 2);
                        p1 &= ~(1u << k);
                    }
                }
            }
            unsigned ready = p2 & ~p1;
            if (ready) {
                unsigned dw[7], kw[7];
                #pragma unroll
                for (int r = 0; r < 7; r++) {
                    int ry = y0 - 2 + r;
                    if ((unsigned)ry < WW) {
                        int base = ry * 4 + w;
                        dw[r] = __funnelshift_r(dec2[base],  dec2[base + 1],  sh) & 0x1FFu;
                        kw[r] = __funnelshift_r(kept2[base], kept2[base + 1], sh) & 0x1FFu;
                    } else { dw[r] = 0; kw[r] = 0; }
                }
                #pragma unroll
                for (int k = 0; k < 9; k++) {
                    if (!(ready & (1u << k))) continue;
                    int ry = k / 3, cx = k % 3;
                    unsigned n2 = (unsigned)(m2all >> (4 * k)) & 15u;
                    unsigned supp =
                          ((n2 >> 0) & (kw[ry + 1] >> (cx + 2)))
                        | ((n2 >> 1) & (kw[ry + 2] >> (cx + 1)))
                        | ((n2 >> 2) & (kw[ry + 2] >> (cx + 3)))
                        | ((n2 >> 3) & (kw[ry + 3] >> (cx + 2)));
                    unsigned und =
                          ((n2 >> 0) & ((~dw[ry + 1]) >> (cx + 2)))
                        | ((n2 >> 1) & ((~dw[ry + 2]) >> (cx + 1)))
                        | ((n2 >> 2) & ((~dw[ry + 2]) >> (cx + 3)))
                        | ((n2 >> 3) & ((~dw[ry + 3]) >> (cx + 2)));
                    int x = x0 + cx, y = y0 + ry;
                    if (supp & 1u) {
                        set_bit_s(dec2, x, y);
                        dw[ry + 2] |= 1u << (cx + 2);
                        p2 &= ~(1u << k);
                    } else if (!(und & 1u)) {
                        set_bit_s(dec2, x, y); set_bit_s(kept2, x, y);
                        dw[ry + 2] |= 1u << (cx + 2);
                        kw[ry + 2] |= 1u << (cx + 2);
                        p2 &= ~(1u << k);
                    }
                }
            }
        }
        if (__syncthreads_and((p1 | p2) == 0)) break;
    }
    // kept2 now holds the final keep map; barrier above makes it visible.

    // ---- Phase 5: epilogue (rank from shared, regress, scatter) ----
    #pragma unroll
    for (int k = 0; k < 9; k++) {
        int c = t + k * 1024;
        float s = sc[c];
        int bin = min((int)(s * 8192.0f), NB - 1);
        unsigned packed = hist[bin];
        unsigned rank = packed & 0xFFFFu;
        unsigned cnt  = packed >> 16;
        if (cnt > 1u) {
            if (cnt <= CAP) {
                for (unsigned j = 0; j < cnt; j++) {
                    int idx = (int)list[bin * CAP + j];
                    float sj = sc[idx];
                    rank += (sj > s) || (sj == s && idx < c);
                }
            } else {        // overflow fallback: exact recount from shared
                rank = 0;
                for (int j = 0; j < NN; j++) {
                    float sj = sc[j];
                    rank += (sj > s) || (sj == s && j < c);
                }
            }
        }
        int x = c % WW, y = c / WW, p = x + 2;
        float kq = ((kept2[y * 4 + (p >> 5)] >> (p & 31)) & 1u) ? 1.0f : 0.0f;
        float X1 = rintf((2.0f * x) / 0.6f);
        float X2 = rintf((2.0f * x + 12.0f) / 0.6f);
        float Y1 = rintf((2.0f * y) / 0.6f);
        float Y2 = rintf((2.0f * y + 12.0f) / 0.6f);
        float bw = X2 - X1 + 1.0f;
        float bh = Y2 - Y1 + 1.0f;
        float4 d = ((const float4*)reg)[c];
        float* o = out + (int)rank * 5;
        o[0] = (X1 + d.x * bw) * kq;
        o[1] = (Y1 + d.y * bh) * kq;
        o[2] = (X2 + d.z * bw) * kq;
        o[3] = (Y2 + d.w * bh) * kq;
        o[4] = s * kq;
    }
}

extern "C" void kernel_launch(void* const* d_in, const int* in_sizes, int n_in,
                              void* d_out, int out_size) {
    const float* cls = (const float*)d_in[0];
    const float* reg = (const float*)d_in[1];
    if (n_in >= 2 && in_sizes[0] > in_sizes[1]) {   // defensive: metadata order
        const float* t = cls; cls = reg; reg = t;
    }
    float* out = (float*)d_out;

    cudaFuncSetAttribute(fused_kernel,
                         cudaFuncAttributeMaxDynamicSharedMemorySize, SMEM_BYTES);
    fused_kernel<<<1, 1024, SMEM_BYTES>>>(cls, reg, out);
}

// round 16
// speedup vs baseline: 2.1436x; 1.5467x over previous
#include <cuda_runtime.h>
#include <cuda_bf16.h>

#define NN 9216
#define WW 96
#define NB 8192
#define CAP 8

// Dynamic shared layout for kernel A (200704 B, needs func attribute):
//   [0)      float    sc[9216]      36864
//   [36864)  unsigned hist[8192]    32768   (packed binstart | cnt<<16 after scan)
//   [69632)  ushort   list[8192*8] 131072
#define SMEM_BYTES 200704

// Cross-kernel handoff: rank | (keep << 31), written coalesced by kernel A.
__device__ unsigned g_rankkeep[NN];

__device__ __forceinline__ void set_bit_s(unsigned* arr, int x, int y) {
    int p = x + 2;
    atomicOr(&arr[y * 4 + (p >> 5)], 1u << (p & 31));
}

// ---------------------------------------------------------------------------
// Kernel A: hist + scan + NMS fixpoint + rank/keep pack (NO scattered writes —
// the single-SM L1 wavefront bound killed R14's in-kernel scatter).
// ---------------------------------------------------------------------------
__global__ void __launch_bounds__(1024, 1) nms_rank_kernel(const float* __restrict__ cls) {
    extern __shared__ unsigned char dynsmem[];
    float*          sc   = (float*)dynsmem;
    unsigned*       hist = (unsigned*)(dynsmem + 36864);
    unsigned short* list = (unsigned short*)(dynsmem + 69632);

    // Hot fixpoint state: STATIC shared (R9-proven band-mapped engine).
    __shared__ unsigned dec1[WW * 4], kept1[WW * 4], dec2[WW * 4], kept2[WW * 4];
    __shared__ unsigned wsum[32];

    const int t    = threadIdx.x;
    const int lane = t & 31, wid = t >> 5;
    const int tx = t & 31, ty = t >> 5;          // band mapping (R9)
    const int x0 = 3 * tx, y0 = 3 * ty;
    const int w  = x0 >> 5, sh = x0 & 31;

    // ---- Phase 0: zero hist + bit arrays ----
    #pragma unroll
    for (int i = 0; i < 8; i++) hist[t * 8 + i] = 0;
    if (t < WW * 4) { dec1[t] = 0; kept1[t] = 0; dec2[t] = 0; kept2[t] = 0; }
    __syncthreads();

    // ---- Phase 1: load scores; shared histogram + tie lists ----
    #pragma unroll
    for (int k = 0; k < 9; k++) {
        int c = t + k * 1024;
        float s = cls[c];
        sc[c] = s;
        int bin = min((int)(s * 8192.0f), NB - 1);
        unsigned slot = atomicAdd(&hist[bin], 1u);
        if (slot < CAP) list[bin * CAP + slot] = (unsigned short)c;
    }
    __syncthreads();

    // ---- Phase 2: 8192-bin scan (shuffle-based, proven) ----
    {
        unsigned v[8], sum = 0;
        #pragma unroll
        for (int i = 0; i < 8; i++) { v[i] = hist[t * 8 + i]; sum += v[i]; }
        unsigned s = sum;
        #pragma unroll
        for (int off = 1; off < 32; off <<= 1) {
            unsigned n = __shfl_up_sync(0xFFFFFFFFu, s, off);
            if (lane >= off) s += n;
        }
        if (lane == 31) wsum[wid] = s;
        __syncthreads();
        if (wid == 0) {
            unsigned ws = wsum[lane];
            #pragma unroll
            for (int off = 1; off < 32; off <<= 1) {
                unsigned n = __shfl_up_sync(0xFFFFFFFFu, ws, off);
                if (lane >= off) ws += n;
            }
            wsum[lane] = ws;
        }
        __syncthreads();
        unsigned run = (wid ? wsum[wid - 1] : 0u) + s - sum;
        #pragma unroll
        for (int i = 0; i < 8; i++) {
            run += v[i];
            hist[t * 8 + i] = (unsigned)(NN - run) | (v[i] << 16);
        }
    }

    // ---- Phase 3: build masks + init invalid cells (proven R9 logic) ----
    unsigned m1[9];
    unsigned long long m2all = 0;
    unsigned pend = 0;
    #pragma unroll
    for (int k = 0; k < 9; k++) {
        int ry = k / 3, cx = k % 3;
        int x = x0 + cx, y = y0 + ry;
        int c = y * WW + x;
        float s = sc[c];
        unsigned mm1 = 0, n2 = 0;
        if (s > 0.6f) {
            pend |= 1u << k;
            int xm = x % 3, ym = y % 3;
            #define EARLIER(n) (sc[(n)] > s || (sc[(n)] == s && (n) < c))
            if (x > 0  && EARLIER(c - 1))  { mm1 |= 1u << 11; if (xm != 2) n2 |= 2u; }
            if (x < 95 && EARLIER(c + 1))  { mm1 |= 1u << 13; if (xm != 1) n2 |= 4u; }
            if (y > 0  && EARLIER(c - 96)) { mm1 |= 1u << 7;  if (ym != 2) n2 |= 1u; }
            if (y < 95 && EARLIER(c + 96)) { mm1 |= 1u << 17; if (ym != 1) n2 |= 8u; }
            if (x > 1  && xm == 1 && EARLIER(c - 2))   mm1 |= 1u << 10;
            if (x < 94 && xm == 2 && EARLIER(c + 2))   mm1 |= 1u << 14;
            if (y > 1  && ym == 1 && EARLIER(c - 192)) mm1 |= 1u << 2;
            if (y < 94 && ym == 2 && EARLIER(c + 192)) mm1 |= 1u << 22;
            bool sxp4 = (xm == 1), sxm4 = (xm == 2), syp4 = (ym == 1), sym4 = (ym == 2);
            if (x > 0  && y > 0  && !(sxm4 && sym4) && EARLIER(c - 97)) mm1 |= 1u << 6;
            if (x < 95 && y > 0  && !(sxp4 && sym4) && EARLIER(c - 95)) mm1 |= 1u << 8;
            if (x > 0  && y < 95 && !(sxm4 && syp4) && EARLIER(c + 95)) mm1 |= 1u << 16;
            if (x < 95 && y < 95 && !(sxp4 && syp4) && EARLIER(c + 97)) mm1 |= 1u << 18;
            #undef EARLIER
        } else {
            set_bit_s(dec1, x, y);
            set_bit_s(dec2, x, y);
        }
        m1[k] = mm1;
        m2all |= (unsigned long long)n2 << (4 * k);
    }
    __syncthreads();

    // ---- Phase 4: deterministic barrier rounds (byte-equal R9 engine) ----
    unsigned p1 = pend, p2 = pend;
    for (;;) {
        #pragma unroll
        for (int rep = 0; rep < 2; rep++) {
            if (p1) {
                unsigned dw[7], kw[7];
                #pragma unroll
                for (int r = 0; r < 7; r++) {
                    int ry = y0 - 2 + r;
                    if ((unsigned)ry < WW) {
                        int base = ry * 4 + w;
                        dw[r] = __funnelshift_r(dec1[base],  dec1[base + 1],  sh) & 0x1FFu;
                        kw[r] = __funnelshift_r(kept1[base], kept1[base + 1], sh) & 0x1FFu;
                    } else { dw[r] = 0; kw[r] = 0; }
                }
                #pragma unroll
                for (int k = 0; k < 9; k++) {
                    if (!(p1 & (1u << k))) continue;
                    int ry = k / 3, cx = k % 3;
                    unsigned mk = m1[k], supp = 0, und = 0;
                    #pragma unroll
                    for (int r = 0; r < 5; r++) {
                        unsigned mrow = (mk >> (5 * r)) & 31u;
                        supp |= mrow & (kw[ry + r] >> cx);
                        und  |= mrow & ((~dw[ry + r]) >> cx);
                    }
                    int x = x0 + cx, y = y0 + ry;
                    if (supp) {
                        set_bit_s(dec1, x, y); set_bit_s(dec2, x, y);
                        dw[ry + 2] |= 1u << (cx + 2);
                        p1 &= ~(1u << k); p2 &= ~(1u << k);
                    } else if (!und) {
                        set_bit_s(dec1, x, y); set_bit_s(kept1, x, y);
                        dw[ry + 2] |= 1u << (cx + 2);
                        kw[ry + 2] |= 1u << (cx + 2);
                        p1 &= ~(1u << k);
                    }
                }
            }
            unsigned ready = p2 & ~p1;
            if (ready) {
                unsigned dw[7], kw[7];
                #pragma unroll
                for (int r = 0; r < 7; r++) {
                    int ry = y0 - 2 + r;
                    if ((unsigned)ry < WW) {
                        int base = ry * 4 + w;
                        dw[r] = __funnelshift_r(dec2[base],  dec2[base + 1],  sh) & 0x1FFu;
                        kw[r] = __funnelshift_r(kept2[base], kept2[base + 1], sh) & 0x1FFu;
                    } else { dw[r] = 0; kw[r] = 0; }
                }
                #pragma unroll
                for (int k = 0; k < 9; k++) {
                    if (!(ready & (1u << k))) continue;
                    int ry = k / 3, cx = k % 3;
                    unsigned n2 = (unsigned)(m2all >> (4 * k)) & 15u;
                    unsigned supp =
                          ((n2 >> 0) & (kw[ry + 1] >> (cx + 2)))
                        | ((n2 >> 1) & (kw[ry + 2] >> (cx + 1)))
                        | ((n2 >> 2) & (kw[ry + 2] >> (cx + 3)))
                        | ((n2 >> 3) & (kw[ry + 3] >> (cx + 2)));
                    unsigned und =
                          ((n2 >> 0) & ((~dw[ry + 1]) >> (cx + 2)))
                        | ((n2 >> 1) & ((~dw[ry + 2]) >> (cx + 1)))
                        | ((n2 >> 2) & ((~dw[ry + 2]) >> (cx + 3)))
                        | ((n2 >> 3) & ((~dw[ry + 3]) >> (cx + 2)));
                    int x = x0 + cx, y = y0 + ry;
                    if (supp & 1u) {
                        set_bit_s(dec2, x, y);
                        dw[ry + 2] |= 1u << (cx + 2);
                        p2 &= ~(1u << k);
                    } else if (!(und & 1u)) {
                        set_bit_s(dec2, x, y); set_bit_s(kept2, x, y);
                        dw[ry + 2] |= 1u << (cx + 2);
                        kw[ry + 2] |= 1u << (cx + 2);
                        p2 &= ~(1u << k);
                    }
                }
            }
        }
        if (__syncthreads_and((p1 | p2) == 0)) break;
    }

    // ---- Phase 5: rank + keep pack, COALESCED write only ----
    #pragma unroll
    for (int k = 0; k < 9; k++) {
        int c = t + k * 1024;
        float s = sc[c];
        int bin = min((int)(s * 8192.0f), NB - 1);
        unsigned packed = hist[bin];
        unsigned rank = packed & 0xFFFFu;
        unsigned cnt  = packed >> 16;
        if (cnt > 1u) {
            if (cnt <= CAP) {
                for (unsigned j = 0; j < cnt; j++) {
                    int idx = (int)list[bin * CAP + j];
                    float sj = sc[idx];
                    rank += (sj > s) || (sj == s && idx < c);
                }
            } else {        // overflow fallback: exact recount from shared
                rank = 0;
                for (int j = 0; j < NN; j++) {
                    float sj = sc[j];
                    rank += (sj > s) || (sj == s && j < c);
                }
            }
        }
        int x = c % WW, y = c / WW, p = x + 2;
        unsigned keep = (kept2[y * 4 + (p >> 5)] >> (p & 31)) & 1u;
        g_rankkeep[c] = rank | (keep << 31);
    }
}

// ---------------------------------------------------------------------------
// Kernel B: multi-SM scatter epilogue (short independent-load chain).
// ---------------------------------------------------------------------------
__global__ void __launch_bounds__(256) epi_kernel(const float* __restrict__ cls,
                                                  const float* __restrict__ reg,
                                                  float* __restrict__ out) {
    const int c = blockIdx.x * 256 + threadIdx.x;
    unsigned rk = g_rankkeep[c];
    float s  = cls[c];
    float4 d = ((const float4*)reg)[c];
    float kq = (rk >> 31) ? 1.0f : 0.0f;
    int rank = (int)(rk & 0xFFFFu);
    int x = c % WW, y = c / WW;
    float X1 = rintf((2.0f * x) / 0.6f);
    float X2 = rintf((2.0f * x + 12.0f) / 0.6f);
    float Y1 = rintf((2.0f * y) / 0.6f);
    float Y2 = rintf((2.0f * y + 12.0f) / 0.6f);
    float bw = X2 - X1 + 1.0f;
    float bh = Y2 - Y1 + 1.0f;
    float* o = out + rank * 5;
    o[0] = (X1 + d.x * bw) * kq;
    o[1] = (Y1 + d.y * bh) * kq;
    o[2] = (X2 + d.z * bw) * kq;
    o[3] = (Y2 + d.w * bh) * kq;
    o[4] = s * kq;
}

extern "C" void kernel_launch(void* const* d_in, const int* in_sizes, int n_in,
                              void* d_out, int out_size) {
    const float* cls = (const float*)d_in[0];
    const float* reg = (const float*)d_in[1];
    if (n_in >= 2 && in_sizes[0] > in_sizes[1]) {   // defensive: metadata order
        const float* t = cls; cls = reg; reg = t;
    }
    float* out = (float*)d_out;

    cudaFuncSetAttribute(nms_rank_kernel,
                         cudaFuncAttributeMaxDynamicSharedMemorySize, SMEM_BYTES);

    nms_rank_kernel<<<1, 1024, SMEM_BYTES>>>(cls);
    epi_kernel<<<36, 256>>>(cls, reg, out);
}